// round 10
// baseline (speedup 1.0000x reference)
#include <cuda_runtime.h>
#include <cuda_fp16.h>
#include <cstdint>
#include <math.h>
#include <mma.h>

using namespace nvcuda;

// ---------------------------------------------------------------------------
// Model constants
// ---------------------------------------------------------------------------
#define BB       8
#define LL       2048
#define BLTOT    (BB*LL)        // 16384
#define DM       512
#define DI       1024           // d_inner
#define DS       16             // d_state
#define DTR      32             // dt_rank
#define XDW      64             // dt_rank + 2*d_state
#define NL       4
#define DCONV    4
#define DHID     256
// scan chunking
#define NCHUNK   64
#define CLEN     (LL/NCHUNK)    // 32
#define NCHAIN   (BB*DI)        // 8192
// conv strip length
#define LCH      32

// ---------------------------------------------------------------------------
// Scratch (device globals; allocation APIs are forbidden)
// ---------------------------------------------------------------------------
__device__ __half g_x0  [BLTOT*DM];
__device__ __half g_x1  [BLTOT*DM];
__device__ __half g_xz  [(size_t)BLTOT*2*DI];
__device__ __half g_u   [BLTOT*DI];
__device__ float  g_xdbl[BLTOT*XDW];
__device__ __half g_y   [BLTOT*DI];
__device__ float  g_E   [NCHUNK*DS*NCHAIN];
__device__ float  g_P   [NCHUNK*DS*NCHAIN];
__device__ float  g_Hi  [NCHUNK*DS*NCHAIN];
// fp16 weight copies (converted each launch)
__device__ __half g_Whin [NL*2*DI*DM];
__device__ __half g_Whxp [NL*XDW*DI];
__device__ __half g_Whout[NL*DM*DI];

__device__ __forceinline__ unsigned int h2u(__half2 h)
{
    return *(unsigned int*)&h;
}

// ---------------------------------------------------------------------------
// FMA-only transcendentals
// ---------------------------------------------------------------------------
__device__ __forceinline__ float fexp(float x)
{
    x = fminf(fmaxf(x, -87.0f), 87.0f);
    float t = x * 1.4426950408889634f;
    float z = t + 12582912.0f;
    int   ir = __float_as_int(z) - 0x4B400000;
    float r = z - 12582912.0f;
    float f = t - r;
    float p =            1.535336188319500e-4f;
    p = fmaf(p, f, 1.339887440266574e-3f);
    p = fmaf(p, f, 9.618437357674640e-3f);
    p = fmaf(p, f, 5.550332471162809e-2f);
    p = fmaf(p, f, 2.402264791363012e-1f);
    p = fmaf(p, f, 6.931472028550421e-1f);
    p = fmaf(p, f, 1.0f);
    return p * __int_as_float((ir + 127) << 23);
}

__device__ __forceinline__ float flog(float y)
{
    int i = __float_as_int(y);
    int e = (i - 0x3f3504f3) >> 23;
    float m = __int_as_float(i - (e << 23));
    float f = m - 1.0f;
    float zz = f * f;
    float p =            7.0376836292e-2f;
    p = fmaf(p, f, -1.1514610310e-1f);
    p = fmaf(p, f,  1.1676998740e-1f);
    p = fmaf(p, f, -1.2420140846e-1f);
    p = fmaf(p, f,  1.4249322787e-1f);
    p = fmaf(p, f, -1.6668057665e-1f);
    p = fmaf(p, f,  2.0000714765e-1f);
    p = fmaf(p, f, -2.4999993993e-1f);
    p = fmaf(p, f,  3.3333331174e-1f);
    float r = p * (f * zz);
    r = fmaf(-0.5f, zz, r);
    r = r + f;
    r = fmaf((float)e, 0.69314718055994531f, r);
    return r;
}

__device__ __forceinline__ float fsigmoid(float x)
{
    float e = fexp(-fabsf(x));
    float d = 1.0f + e;
    float r = fmaf(-0.5f, d, 1.457107f);
    r = r * fmaf(-d, r, 2.0f);
    r = r * fmaf(-d, r, 2.0f);
    r = r * fmaf(-d, r, 2.0f);
    return x >= 0.f ? r : 1.0f - r;
}

__device__ __forceinline__ float fsoftplus(float v)
{
    return flog(1.0f + fexp(v));
}

// ---------------------------------------------------------------------------
// fp32 -> fp16 weight conversion
// ---------------------------------------------------------------------------
__global__ void cvt_kernel(const float* __restrict__ src, __half* __restrict__ dst, int n)
{
    int i = blockIdx.x*256 + threadIdx.x;
    if (i < n) dst[i] = __float2half(src[i]);
}

// ---------------------------------------------------------------------------
// Embedding, vectorized: 8 halfs (16B) per thread
// ---------------------------------------------------------------------------
__global__ void embed_kernel(const int* __restrict__ rna,
                             const int* __restrict__ tissue,
                             const float* __restrict__ seq_emb,
                             const float* __restrict__ tis_emb,
                             __half* __restrict__ x)
{
    int i = blockIdx.x*256 + threadIdx.x;          // over BLTOT*DM/8
    if (i >= BLTOT*DM/8) return;
    int dd = (i & (DM/8 - 1)) * 8;
    int bl = i >> 6;                                // DM/8 = 64
    int b  = bl >> 11;
    int tok = rna[bl];
    uint4 outv;
    if (tok != 0) {
        const float4* s = (const float4*)(seq_emb + tok*DM + dd);
        const float4* t = (const float4*)(tis_emb + tissue[b]*DM + dd);
        float4 s0 = s[0], s1 = s[1];
        float4 t0 = t[0], t1 = t[1];
        __half2 h0 = __floats2half2_rn(s0.x+t0.x, s0.y+t0.y);
        __half2 h1 = __floats2half2_rn(s0.z+t0.z, s0.w+t0.w);
        __half2 h2 = __floats2half2_rn(s1.x+t1.x, s1.y+t1.y);
        __half2 h3 = __floats2half2_rn(s1.z+t1.z, s1.w+t1.w);
        outv.x = h2u(h0); outv.y = h2u(h1);
        outv.z = h2u(h2); outv.w = h2u(h3);
    } else {
        outv.x = outv.y = outv.z = outv.w = 0u;
    }
    *(uint4*)(x + (size_t)bl*DM + dd) = outv;
}

// ---------------------------------------------------------------------------
// fp16 tensor-core GEMM: C[M,N] = A[M,K] * W[N,K]^T
// ---------------------------------------------------------------------------
template<int BM,int BN,int BK,int WM,int WN,int NT, typename CT>
__global__ __launch_bounds__(NT)
void gemm_h(const __half* __restrict__ A, int lda,
            const __half* __restrict__ W, int ldb,
            CT* __restrict__ C, int ldc, int K)
{
    constexpr bool HALF_OUT = (sizeof(CT) == 2);
    constexpr int LDSH = BK + 8;
    constexpr int STG  = 3;
    constexpr int ABUF = BM*LDSH;
    constexpr int BBUF = BN*LDSH;
    constexpr int WCOLS = BN/WN;
    constexpr int TM = WM/16, TN = WN/16;

    extern __shared__ __align__(16) unsigned char smem_raw[];
    __half* As = (__half*)smem_raw;
    __half* Bs = As + STG*ABUF;

    const int tid = threadIdx.x;
    const int wid = tid >> 5;
    const int wr  = wid / WCOLS;
    const int wc  = wid % WCOLS;
    const int m0  = blockIdx.y*BM;
    const int n0  = blockIdx.x*BN;

    wmma::fragment<wmma::accumulator,16,16,16,float> acc[TM][TN];
    #pragma unroll
    for (int i=0;i<TM;i++)
        #pragma unroll
        for (int j=0;j<TN;j++) wmma::fill_fragment(acc[i][j], 0.f);

    constexpr int AIT = (BM*BK)/(8*NT);
    constexpr int BIT = (BN*BK)/(8*NT);
    static_assert(AIT >= 1 && BIT >= 1, "tile/thread mismatch");

    auto issue = [&](int kt, int buf){
        int k0 = kt*BK;
        __half* as = As + buf*ABUF;
        __half* bs = Bs + buf*BBUF;
        #pragma unroll
        for (int i=0;i<AIT;i++){
            int q = tid + i*NT;
            int r = q / (BK/8); int c = (q % (BK/8))*8;
            unsigned int d = (unsigned int)__cvta_generic_to_shared(as + r*LDSH + c);
            const __half* s = A + (size_t)(m0+r)*lda + k0 + c;
            asm volatile("cp.async.cg.shared.global [%0],[%1],16;\n" :: "r"(d), "l"(s));
        }
        #pragma unroll
        for (int i=0;i<BIT;i++){
            int q = tid + i*NT;
            int r = q / (BK/8); int c = (q % (BK/8))*8;
            unsigned int d = (unsigned int)__cvta_generic_to_shared(bs + r*LDSH + c);
            const __half* s = W + (size_t)(n0+r)*ldb + k0 + c;
            asm volatile("cp.async.cg.shared.global [%0],[%1],16;\n" :: "r"(d), "l"(s));
        }
        asm volatile("cp.async.commit_group;\n");
    };

    const int KT = K/BK;
    issue(0, 0);
    if (KT > 1) issue(1, 1);

    for (int kt=0; kt<KT; kt++){
        if (kt+2 < KT) {
            issue(kt+2, (kt+2)%STG);
            asm volatile("cp.async.wait_group 2;\n");
        } else if (kt+1 < KT) {
            asm volatile("cp.async.wait_group 1;\n");
        } else {
            asm volatile("cp.async.wait_group 0;\n");
        }
        __syncthreads();

        const __half* as = As + (kt%STG)*ABUF;
        const __half* bs = Bs + (kt%STG)*BBUF;
        #pragma unroll
        for (int kk=0; kk<BK/16; kk++){
            wmma::fragment<wmma::matrix_a,16,16,16,__half,wmma::row_major> af[TM];
            wmma::fragment<wmma::matrix_b,16,16,16,__half,wmma::col_major> bf[TN];
            #pragma unroll
            for (int i=0;i<TM;i++)
                wmma::load_matrix_sync(af[i], as + (wr*WM + i*16)*LDSH + kk*16, LDSH);
            #pragma unroll
            for (int j=0;j<TN;j++)
                wmma::load_matrix_sync(bf[j], bs + (wc*WN + j*16)*LDSH + kk*16, LDSH);
            #pragma unroll
            for (int i=0;i<TM;i++)
                #pragma unroll
                for (int j=0;j<TN;j++)
                    wmma::mma_sync(acc[i][j], af[i], bf[j], acc[i][j]);
        }
        __syncthreads();
    }

    if (HALF_OUT) {
        float* stage = (float*)smem_raw + wid*WM*WN;
        #pragma unroll
        for (int i=0;i<TM;i++)
            #pragma unroll
            for (int j=0;j<TN;j++)
                wmma::store_matrix_sync(stage + (i*16)*WN + j*16, acc[i][j], WN,
                                        wmma::mem_row_major);
        __syncwarp();
        __half* Cw = (__half*)C + (size_t)(m0 + wr*WM)*ldc + n0 + wc*WN;
        const int lane = tid & 31;
        #pragma unroll 4
        for (int q = lane; q < WM*WN/2; q += 32) {
            int row = q / (WN/2);
            int cc  = (q % (WN/2))*2;
            float2 v = *(float2*)(stage + row*WN + cc);
            *(__half2*)(Cw + (size_t)row*ldc + cc) = __floats2half2_rn(v.x, v.y);
        }
    } else {
        #pragma unroll
        for (int i=0;i<TM;i++)
            #pragma unroll
            for (int j=0;j<TN;j++){
                float* cp = (float*)C + (size_t)(m0 + wr*WM + i*16)*ldc + n0 + wc*WN + j*16;
                wmma::store_matrix_sync(cp, acc[i][j], ldc, wmma::mem_row_major);
            }
    }
}

#define GH_BIG_PIPE  (3*(128*(32+8) + 128*(32+8))*2)
#define GH_BIG_STAGE (4*64*64*4)
#define GH_BIG_SMEM  (GH_BIG_STAGE > GH_BIG_PIPE ? GH_BIG_STAGE : GH_BIG_PIPE)
#define GH_XP_SMEM   (3*(64*(64+8) + 64*(64+8))*2)

// ---------------------------------------------------------------------------
// Causal depthwise conv (k=4) + bias + SiLU — rolling window, half2 channels.
// ---------------------------------------------------------------------------
__global__ __launch_bounds__(256)
void conv_silu_kernel(const __half* __restrict__ xz,
                      const float* __restrict__ cw,
                      const float* __restrict__ cb,
                      __half* __restrict__ u)
{
    int i = blockIdx.x*256 + threadIdx.x;   // over BB*(LL/LCH)*(DI/2)
    if (i >= BB*(LL/LCH)*(DI/2)) return;
    int c2 = i & (DI/2 - 1);                // channel pair
    int t  = i >> 9;                        // DI/2 = 512
    int lc = t & (LL/LCH - 1);              // LL/LCH = 64
    int b  = t >> 6;
    int c  = c2*2;

    float4 wa = *(const float4*)(cw + c*DCONV);
    float4 wb = *(const float4*)(cw + (c+1)*DCONV);
    float cba = cb[c], cbb = cb[c+1];

    const int l0 = lc*LCH;
    const __half2* src = (const __half2*)xz + (size_t)(b*LL)*DI + c2;  // stride DI half2/l
    __half2* dst = (__half2*)u + (size_t)(b*LL)*(DI/2) + c2;           // stride DI/2 per l

    float2 x0 = make_float2(0.f,0.f), x1 = x0, x2 = x0;
    if (l0 >= 3) {
        x0 = __half22float2(src[(size_t)(l0-3)*DI]);
        x1 = __half22float2(src[(size_t)(l0-2)*DI]);
        x2 = __half22float2(src[(size_t)(l0-1)*DI]);
    } else {
        if (l0-3 >= 0) x0 = __half22float2(src[(size_t)(l0-3)*DI]);
        if (l0-2 >= 0) x1 = __half22float2(src[(size_t)(l0-2)*DI]);
        if (l0-1 >= 0) x2 = __half22float2(src[(size_t)(l0-1)*DI]);
    }

    #pragma unroll 8
    for (int l = l0; l < l0+LCH; l++) {
        float2 x3 = __half22float2(src[(size_t)l*DI]);
        float va = cba, vb = cbb;
        va = fmaf(x0.x, wa.x, va); vb = fmaf(x0.y, wb.x, vb);
        va = fmaf(x1.x, wa.y, va); vb = fmaf(x1.y, wb.y, vb);
        va = fmaf(x2.x, wa.z, va); vb = fmaf(x2.y, wb.z, vb);
        va = fmaf(x3.x, wa.w, va); vb = fmaf(x3.y, wb.w, vb);
        va = va * fsigmoid(va);
        vb = vb * fsigmoid(vb);
        dst[(size_t)l*(DI/2)] = __floats2half2_rn(va, vb);
        x0 = x1; x1 = x2; x2 = x3;
    }
}

// ---------------------------------------------------------------------------
// Selective scan, chunked two-pass, dt-GEMM fused
// ---------------------------------------------------------------------------
__global__ __launch_bounds__(128)
void scan_phaseA(const __half* __restrict__ u,
                 const float* __restrict__ xdbl,
                 const float* __restrict__ Wdt,
                 const float* __restrict__ bdt,
                 const float* __restrict__ Alog,
                 float* __restrict__ E,
                 float* __restrict__ P)
{
    const int d = blockIdx.x*128 + threadIdx.x;
    const int g = blockIdx.y;
    const int b = blockIdx.z;
    const int chain = b*DI + d;

    __shared__ float sW[128*33];
    __shared__ float sX[16][XDW];

    {
        const float* wsrc = Wdt + (size_t)(blockIdx.x*128)*DTR;
        for (int idx = threadIdx.x; idx < 128*DTR; idx += 128) {
            int j = idx >> 5, r = idx & 31;
            sW[j*33 + r] = wsrc[idx];
        }
    }
    __syncthreads();
    float Wr[DTR];
    #pragma unroll
    for (int r=0;r<DTR;r++) Wr[r] = sW[threadIdx.x*33 + r];
    const float bd = bdt[d];

    float A[DS];
    #pragma unroll
    for (int n=0;n<DS;n++) A[n] = -fexp(Alog[d*DS+n]);
    bool fast = true;
    #pragma unroll
    for (int n=1;n<DS;n++)
        fast = fast && (fabsf(A[n] - A[0]*(float)(n+1)) <= 1e-4f*fabsf(A[n]) + 1e-6f);

    float h[DS], ap[DS];
    #pragma unroll
    for (int n=0;n<DS;n++) { h[n]=0.f; ap[n]=1.f; }
    float Pp = 1.f;

    const int bl0 = b*LL + g*CLEN;

    for (int t0=0; t0<CLEN; t0+=16) {
        __syncthreads();
        for (int q=threadIdx.x; q<16*XDW; q+=128) {
            int j = q >> 6, m = q & 63;
            sX[j][m] = xdbl[(bl0+t0+j)*XDW + m];
        }
        __syncthreads();
        for (int t=0;t<16;t++) {
            int idx = bl0 + t0 + t;
            float v = bd;
            #pragma unroll
            for (int r=0;r<DTR;r++) v = fmaf(sX[t][r], Wr[r], v);
            float ldt = fsoftplus(v);
            float s   = ldt * __half2float(u[(size_t)idx*DI + d]);
            if (fast) {
                float p = fexp(ldt*A[0]);
                Pp *= p;
                float pw = p;
                #pragma unroll
                for (int n=0;n<DS;n++) { h[n] = fmaf(pw, h[n], s*sX[t][DTR+n]); pw *= p; }
            } else {
                #pragma unroll
                for (int n=0;n<DS;n++) {
                    float a = fexp(ldt*A[n]);
                    ap[n] *= a;
                    h[n] = fmaf(a, h[n], s*sX[t][DTR+n]);
                }
            }
        }
    }
    if (fast) {
        float pw = Pp;
        #pragma unroll
        for (int n=0;n<DS;n++) { ap[n] = pw; pw *= Pp; }
    }
    #pragma unroll
    for (int n=0;n<DS;n++) {
        E[(g*DS+n)*NCHAIN + chain] = h[n];
        P[(g*DS+n)*NCHAIN + chain] = ap[n];
    }
}

__global__ void scan_phaseB(const float* __restrict__ E,
                            const float* __restrict__ P,
                            float* __restrict__ Hi)
{
    int c = blockIdx.x*256 + threadIdx.x;
    if (c >= NCHAIN) return;
    #pragma unroll
    for (int n=0;n<DS;n++) {
        float carry = 0.f;
        #pragma unroll
        for (int g=0;g<NCHUNK;g++) {
            int o = (g*DS+n)*NCHAIN + c;
            Hi[o] = carry;
            carry = fmaf(P[o], carry, E[o]);
        }
    }
}

__global__ __launch_bounds__(128)
void scan_phaseC(const __half* __restrict__ u,
                 const float* __restrict__ xdbl,
                 const __half* __restrict__ xz,
                 const float* __restrict__ Wdt,
                 const float* __restrict__ bdt,
                 const float* __restrict__ Alog,
                 const float* __restrict__ Dpar,
                 const float* __restrict__ Hi,
                 __half* __restrict__ yout)
{
    const int d = blockIdx.x*128 + threadIdx.x;
    const int g = blockIdx.y;
    const int b = blockIdx.z;
    const int chain = b*DI + d;

    __shared__ float sW[128*33];
    __shared__ float sX[16][XDW];

    {
        const float* wsrc = Wdt + (size_t)(blockIdx.x*128)*DTR;
        for (int idx = threadIdx.x; idx < 128*DTR; idx += 128) {
            int j = idx >> 5, r = idx & 31;
            sW[j*33 + r] = wsrc[idx];
        }
    }
    __syncthreads();
    float Wr[DTR];
    #pragma unroll
    for (int r=0;r<DTR;r++) Wr[r] = sW[threadIdx.x*33 + r];
    const float bd = bdt[d];

    float A[DS];
    #pragma unroll
    for (int n=0;n<DS;n++) A[n] = -fexp(Alog[d*DS+n]);
    bool fast = true;
    #pragma unroll
    for (int n=1;n<DS;n++)
        fast = fast && (fabsf(A[n] - A[0]*(float)(n+1)) <= 1e-4f*fabsf(A[n]) + 1e-6f);

    float h[DS];
    #pragma unroll
    for (int n=0;n<DS;n++) h[n] = Hi[(g*DS+n)*NCHAIN + chain];
    const float Dp = Dpar[d];

    const int bl0 = b*LL + g*CLEN;

    for (int t0=0; t0<CLEN; t0+=16) {
        __syncthreads();
        for (int q=threadIdx.x; q<16*XDW; q+=128) {
            int j = q >> 6, m = q & 63;
            sX[j][m] = xdbl[(bl0+t0+j)*XDW + m];
        }
        __syncthreads();
        for (int t=0;t<16;t++) {
            int idx = bl0 + t0 + t;
            float v = bd;
            #pragma unroll
            for (int r=0;r<DTR;r++) v = fmaf(sX[t][r], Wr[r], v);
            float ldt = fsoftplus(v);
            float lu  = __half2float(u[(size_t)idx*DI + d]);
            float s   = ldt * lu;
            float y   = 0.f;
            if (fast) {
                float p = fexp(ldt*A[0]);
                float pw = p;
                #pragma unroll
                for (int n=0;n<DS;n++) {
                    h[n] = fmaf(pw, h[n], s*sX[t][DTR+n]);
                    y    = fmaf(h[n], sX[t][DTR+DS+n], y);
                    pw *= p;
                }
            } else {
                #pragma unroll
                for (int n=0;n<DS;n++) {
                    float a = fexp(ldt*A[n]);
                    h[n] = fmaf(a, h[n], s*sX[t][DTR+n]);
                    y    = fmaf(h[n], sX[t][DTR+DS+n], y);
                }
            }
            float z = __half2float(xz[(size_t)idx*(2*DI) + DI + d]);
            yout[(size_t)idx*DI + d] = __float2half((y + lu*Dp) * z * fsigmoid(z));
        }
    }
}

// ---------------------------------------------------------------------------
// Head
// ---------------------------------------------------------------------------
__global__ void head_kernel(const __half* __restrict__ x,
                            const int* __restrict__ lens,
                            const float* __restrict__ W1,
                            const float* __restrict__ b1,
                            const float* __restrict__ W2,
                            const float* __restrict__ b2,
                            float* __restrict__ out)
{
    __shared__ float xs[DM];
    __shared__ float red[DHID];
    const int b = blockIdx.x;
    const int tid = threadIdx.x;
    const int l = lens[b] - 1;
    const __half* xr = x + ((size_t)(b*LL + l))*DM;
    for (int i=tid; i<DM; i+=DHID) xs[i] = __half2float(xr[i]);
    __syncthreads();
    float acc = b1[tid];
    const float* w = W1 + tid*DM;
    #pragma unroll 4
    for (int d0=0; d0<DM; d0+=4) {
        float4 wv = *(const float4*)(w + d0);
        acc = fmaf(wv.x, xs[d0+0], acc);
        acc = fmaf(wv.y, xs[d0+1], acc);
        acc = fmaf(wv.z, xs[d0+2], acc);
        acc = fmaf(wv.w, xs[d0+3], acc);
    }
    float hh = fmaxf(acc, 0.f);
    red[tid] = hh * W2[tid];
    __syncthreads();
    for (int s=DHID/2; s>0; s>>=1) {
        if (tid < s) red[tid] += red[tid+s];
        __syncthreads();
    }
    if (tid == 0) out[b] = red[0] + b2[0];
}

// ---------------------------------------------------------------------------
// Host launcher
// ---------------------------------------------------------------------------
extern "C" void kernel_launch(void* const* d_in, const int* in_sizes, int n_in,
                              void* d_out, int out_size)
{
    const int*   rna     = (const int*)  d_in[0];
    const int*   tissue  = (const int*)  d_in[1];
    const int*   lens    = (const int*)  d_in[2];
    const float* seq_emb = (const float*)d_in[3];
    const float* tis_emb = (const float*)d_in[4];
    const float* W_in    = (const float*)d_in[5];
    const float* conv_w  = (const float*)d_in[6];
    const float* conv_b  = (const float*)d_in[7];
    const float* W_xp    = (const float*)d_in[8];
    const float* W_dt    = (const float*)d_in[9];
    const float* b_dt    = (const float*)d_in[10];
    const float* A_log   = (const float*)d_in[11];
    const float* D_par   = (const float*)d_in[12];
    const float* W_out   = (const float*)d_in[13];
    const float* W1      = (const float*)d_in[14];
    const float* b1      = (const float*)d_in[15];
    const float* W2      = (const float*)d_in[16];
    const float* b2      = (const float*)d_in[17];

    __half *px0, *px1, *pxz, *pu, *py, *pWhin, *pWhxp, *pWhout;
    float  *pxd, *pE, *pP, *pHi;
    cudaGetSymbolAddress((void**)&px0,   g_x0);
    cudaGetSymbolAddress((void**)&px1,   g_x1);
    cudaGetSymbolAddress((void**)&pxz,   g_xz);
    cudaGetSymbolAddress((void**)&pu,    g_u);
    cudaGetSymbolAddress((void**)&pxd,   g_xdbl);
    cudaGetSymbolAddress((void**)&py,    g_y);
    cudaGetSymbolAddress((void**)&pE,    g_E);
    cudaGetSymbolAddress((void**)&pP,    g_P);
    cudaGetSymbolAddress((void**)&pHi,   g_Hi);
    cudaGetSymbolAddress((void**)&pWhin, g_Whin);
    cudaGetSymbolAddress((void**)&pWhxp, g_Whxp);
    cudaGetSymbolAddress((void**)&pWhout,g_Whout);

    cudaFuncSetAttribute((gemm_h<128,128,32,64,64,128,__half>),
                         cudaFuncAttributeMaxDynamicSharedMemorySize, GH_BIG_SMEM);
    cudaFuncSetAttribute((gemm_h<64,64,64,32,32,128,float>),
                         cudaFuncAttributeMaxDynamicSharedMemorySize, GH_XP_SMEM);

    {
        int n1 = NL*2*DI*DM, n2 = NL*XDW*DI, n3 = NL*DM*DI;
        cvt_kernel<<<(n1+255)/256, 256>>>(W_in,  pWhin,  n1);
        cvt_kernel<<<(n2+255)/256, 256>>>(W_xp,  pWhxp,  n2);
        cvt_kernel<<<(n3+255)/256, 256>>>(W_out, pWhout, n3);
    }

    embed_kernel<<<(BLTOT*DM/8+255)/256, 256>>>(rna, tissue, seq_emb, tis_emb, px0);

    __half* xin  = px0;
    __half* xout = px1;
    for (int i=0; i<NL; i++) {
        // in-proj
        gemm_h<128,128,32,64,64,128,__half>
            <<<dim3((2*DI)/128, BLTOT/128), 128, GH_BIG_SMEM>>>(
            xin, DM, pWhin + (size_t)i*2*DI*DM, DM, pxz, 2*DI, DM);
        // conv + silu (rolling window)
        conv_silu_kernel<<<(BB*(LL/LCH)*(DI/2)+255)/256, 256>>>(
            pxz, conv_w + i*DI*DCONV, conv_b + i*DI, pu);
        // x-proj
        gemm_h<64,64,64,32,32,128,float>
            <<<dim3(XDW/64, BLTOT/64), 128, GH_XP_SMEM>>>(
            pu, DI, pWhxp + (size_t)i*XDW*DI, DI, pxd, XDW, DI);
        // selective scan
        scan_phaseA<<<dim3(DI/128, NCHUNK, BB), 128>>>(
            pu, pxd, W_dt + (size_t)i*DI*DTR, b_dt + i*DI,
            A_log + (size_t)i*DI*DS, pE, pP);
        scan_phaseB<<<(NCHAIN+255)/256, 256>>>(pE, pP, pHi);
        scan_phaseC<<<dim3(DI/128, NCHUNK, BB), 128>>>(
            pu, pxd, pxz, W_dt + (size_t)i*DI*DTR, b_dt + i*DI,
            A_log + (size_t)i*DI*DS, D_par + i*DI, pHi, py);
        // out-proj
        gemm_h<128,128,32,64,64,128,__half>
            <<<dim3(DM/128, BLTOT/128), 128, GH_BIG_SMEM>>>(
            py, DI, pWhout + (size_t)i*DM*DI, DI, xout, DM, DI);

        __half* tmp = xin; xin = xout; xout = tmp;
    }

    head_kernel<<<BB, DHID>>>(xin, lens, W1, b1, W2, b2, (float*)d_out);
}

// round 11
// speedup vs baseline: 1.3936x; 1.3936x over previous
#include <cuda_runtime.h>
#include <cuda_fp16.h>
#include <cstdint>
#include <math.h>
#include <mma.h>

using namespace nvcuda;

// ---------------------------------------------------------------------------
// Model constants
// ---------------------------------------------------------------------------
#define BB       8
#define LL       2048
#define BLTOT    (BB*LL)        // 16384
#define DM       512
#define DI       1024           // d_inner
#define DS       16             // d_state
#define DTR      32             // dt_rank
#define XDW      64             // dt_rank + 2*d_state
#define NL       4
#define DCONV    4
#define DHID     256
// scan chunking
#define NCHUNK   32
#define CLEN     (LL/NCHUNK)    // 64
#define NCHAIN   (BB*DI)        // 8192
// conv strip length
#define LCH      32

// ---------------------------------------------------------------------------
// Scratch (device globals; allocation APIs are forbidden)
// ---------------------------------------------------------------------------
__device__ __half g_x0  [BLTOT*DM];
__device__ __half g_x1  [BLTOT*DM];
__device__ __half g_xz  [(size_t)BLTOT*2*DI];
__device__ __half g_u   [BLTOT*DI];
__device__ float  g_xdbl[BLTOT*XDW];
__device__ __half g_y   [BLTOT*DI];
__device__ float  g_E   [NCHUNK*DS*NCHAIN];
__device__ float  g_P   [NCHUNK*DS*NCHAIN];   // full P (non-fast fallback)
__device__ float  g_Pp  [NCHUNK*NCHAIN];      // scalar Pp (fast path)
__device__ float  g_Hi  [NCHUNK*DS*NCHAIN];
// fp16 weight copies (converted each launch)
__device__ __half g_Whin [NL*2*DI*DM];
__device__ __half g_Whxp [NL*XDW*DI];
__device__ __half g_Whout[NL*DM*DI];

__device__ __forceinline__ unsigned int h2u(__half2 h)
{
    return *(unsigned int*)&h;
}

// ---------------------------------------------------------------------------
// FMA-only transcendentals
// ---------------------------------------------------------------------------
__device__ __forceinline__ float fexp(float x)
{
    x = fminf(fmaxf(x, -87.0f), 87.0f);
    float t = x * 1.4426950408889634f;
    float z = t + 12582912.0f;
    int   ir = __float_as_int(z) - 0x4B400000;
    float r = z - 12582912.0f;
    float f = t - r;
    float p =            1.535336188319500e-4f;
    p = fmaf(p, f, 1.339887440266574e-3f);
    p = fmaf(p, f, 9.618437357674640e-3f);
    p = fmaf(p, f, 5.550332471162809e-2f);
    p = fmaf(p, f, 2.402264791363012e-1f);
    p = fmaf(p, f, 6.931472028550421e-1f);
    p = fmaf(p, f, 1.0f);
    return p * __int_as_float((ir + 127) << 23);
}

__device__ __forceinline__ float flog(float y)
{
    int i = __float_as_int(y);
    int e = (i - 0x3f3504f3) >> 23;
    float m = __int_as_float(i - (e << 23));
    float f = m - 1.0f;
    float zz = f * f;
    float p =            7.0376836292e-2f;
    p = fmaf(p, f, -1.1514610310e-1f);
    p = fmaf(p, f,  1.1676998740e-1f);
    p = fmaf(p, f, -1.2420140846e-1f);
    p = fmaf(p, f,  1.4249322787e-1f);
    p = fmaf(p, f, -1.6668057665e-1f);
    p = fmaf(p, f,  2.0000714765e-1f);
    p = fmaf(p, f, -2.4999993993e-1f);
    p = fmaf(p, f,  3.3333331174e-1f);
    float r = p * (f * zz);
    r = fmaf(-0.5f, zz, r);
    r = r + f;
    r = fmaf((float)e, 0.69314718055994531f, r);
    return r;
}

__device__ __forceinline__ float fsigmoid(float x)
{
    float e = fexp(-fabsf(x));
    float d = 1.0f + e;
    float r = fmaf(-0.5f, d, 1.457107f);
    r = r * fmaf(-d, r, 2.0f);
    r = r * fmaf(-d, r, 2.0f);
    r = r * fmaf(-d, r, 2.0f);
    return x >= 0.f ? r : 1.0f - r;
}

__device__ __forceinline__ float fsoftplus(float v)
{
    return flog(1.0f + fexp(v));
}

// fast-path detector: A[n] == A0*(n+1) within tolerance
__device__ __forceinline__ bool fast_check(const float* __restrict__ Alog, int d,
                                           float* A /* out DS */)
{
    #pragma unroll
    for (int n=0;n<DS;n++) A[n] = -fexp(Alog[d*DS+n]);
    bool fast = true;
    #pragma unroll
    for (int n=1;n<DS;n++)
        fast = fast && (fabsf(A[n] - A[0]*(float)(n+1)) <= 1e-4f*fabsf(A[n]) + 1e-6f);
    return fast;
}

// ---------------------------------------------------------------------------
// fp32 -> fp16 weight conversion
// ---------------------------------------------------------------------------
__global__ void cvt_kernel(const float* __restrict__ src, __half* __restrict__ dst, int n)
{
    int i = blockIdx.x*256 + threadIdx.x;
    if (i < n) dst[i] = __float2half(src[i]);
}

// ---------------------------------------------------------------------------
// Embedding, vectorized: 8 halfs (16B) per thread
// ---------------------------------------------------------------------------
__global__ void embed_kernel(const int* __restrict__ rna,
                             const int* __restrict__ tissue,
                             const float* __restrict__ seq_emb,
                             const float* __restrict__ tis_emb,
                             __half* __restrict__ x)
{
    int i = blockIdx.x*256 + threadIdx.x;
    if (i >= BLTOT*DM/8) return;
    int dd = (i & (DM/8 - 1)) * 8;
    int bl = i >> 6;
    int b  = bl >> 11;
    int tok = rna[bl];
    uint4 outv;
    if (tok != 0) {
        const float4* s = (const float4*)(seq_emb + tok*DM + dd);
        const float4* t = (const float4*)(tis_emb + tissue[b]*DM + dd);
        float4 s0 = s[0], s1 = s[1];
        float4 t0 = t[0], t1 = t[1];
        __half2 h0 = __floats2half2_rn(s0.x+t0.x, s0.y+t0.y);
        __half2 h1 = __floats2half2_rn(s0.z+t0.z, s0.w+t0.w);
        __half2 h2 = __floats2half2_rn(s1.x+t1.x, s1.y+t1.y);
        __half2 h3 = __floats2half2_rn(s1.z+t1.z, s1.w+t1.w);
        outv.x = h2u(h0); outv.y = h2u(h1);
        outv.z = h2u(h2); outv.w = h2u(h3);
    } else {
        outv.x = outv.y = outv.z = outv.w = 0u;
    }
    *(uint4*)(x + (size_t)bl*DM + dd) = outv;
}

// ---------------------------------------------------------------------------
// fp16 tensor-core GEMM: C[M,N] = A[M,K] * W[N,K]^T
// ---------------------------------------------------------------------------
template<int BM,int BN,int BK,int WM,int WN,int NT, typename CT>
__global__ __launch_bounds__(NT)
void gemm_h(const __half* __restrict__ A, int lda,
            const __half* __restrict__ W, int ldb,
            CT* __restrict__ C, int ldc, int K)
{
    constexpr bool HALF_OUT = (sizeof(CT) == 2);
    constexpr int LDSH = BK + 8;
    constexpr int STG  = 3;
    constexpr int ABUF = BM*LDSH;
    constexpr int BBUF = BN*LDSH;
    constexpr int WCOLS = BN/WN;
    constexpr int TM = WM/16, TN = WN/16;

    extern __shared__ __align__(16) unsigned char smem_raw[];
    __half* As = (__half*)smem_raw;
    __half* Bs = As + STG*ABUF;

    const int tid = threadIdx.x;
    const int wid = tid >> 5;
    const int wr  = wid / WCOLS;
    const int wc  = wid % WCOLS;
    const int m0  = blockIdx.y*BM;
    const int n0  = blockIdx.x*BN;

    wmma::fragment<wmma::accumulator,16,16,16,float> acc[TM][TN];
    #pragma unroll
    for (int i=0;i<TM;i++)
        #pragma unroll
        for (int j=0;j<TN;j++) wmma::fill_fragment(acc[i][j], 0.f);

    constexpr int AIT = (BM*BK)/(8*NT);
    constexpr int BIT = (BN*BK)/(8*NT);
    static_assert(AIT >= 1 && BIT >= 1, "tile/thread mismatch");

    auto issue = [&](int kt, int buf){
        int k0 = kt*BK;
        __half* as = As + buf*ABUF;
        __half* bs = Bs + buf*BBUF;
        #pragma unroll
        for (int i=0;i<AIT;i++){
            int q = tid + i*NT;
            int r = q / (BK/8); int c = (q % (BK/8))*8;
            unsigned int d = (unsigned int)__cvta_generic_to_shared(as + r*LDSH + c);
            const __half* s = A + (size_t)(m0+r)*lda + k0 + c;
            asm volatile("cp.async.cg.shared.global [%0],[%1],16;\n" :: "r"(d), "l"(s));
        }
        #pragma unroll
        for (int i=0;i<BIT;i++){
            int q = tid + i*NT;
            int r = q / (BK/8); int c = (q % (BK/8))*8;
            unsigned int d = (unsigned int)__cvta_generic_to_shared(bs + r*LDSH + c);
            const __half* s = W + (size_t)(n0+r)*ldb + k0 + c;
            asm volatile("cp.async.cg.shared.global [%0],[%1],16;\n" :: "r"(d), "l"(s));
        }
        asm volatile("cp.async.commit_group;\n");
    };

    const int KT = K/BK;
    issue(0, 0);
    if (KT > 1) issue(1, 1);

    for (int kt=0; kt<KT; kt++){
        if (kt+2 < KT) {
            issue(kt+2, (kt+2)%STG);
            asm volatile("cp.async.wait_group 2;\n");
        } else if (kt+1 < KT) {
            asm volatile("cp.async.wait_group 1;\n");
        } else {
            asm volatile("cp.async.wait_group 0;\n");
        }
        __syncthreads();

        const __half* as = As + (kt%STG)*ABUF;
        const __half* bs = Bs + (kt%STG)*BBUF;
        #pragma unroll
        for (int kk=0; kk<BK/16; kk++){
            wmma::fragment<wmma::matrix_a,16,16,16,__half,wmma::row_major> af[TM];
            wmma::fragment<wmma::matrix_b,16,16,16,__half,wmma::col_major> bf[TN];
            #pragma unroll
            for (int i=0;i<TM;i++)
                wmma::load_matrix_sync(af[i], as + (wr*WM + i*16)*LDSH + kk*16, LDSH);
            #pragma unroll
            for (int j=0;j<TN;j++)
                wmma::load_matrix_sync(bf[j], bs + (wc*WN + j*16)*LDSH + kk*16, LDSH);
            #pragma unroll
            for (int i=0;i<TM;i++)
                #pragma unroll
                for (int j=0;j<TN;j++)
                    wmma::mma_sync(acc[i][j], af[i], bf[j], acc[i][j]);
        }
        __syncthreads();
    }

    if (HALF_OUT) {
        float* stage = (float*)smem_raw + wid*WM*WN;
        #pragma unroll
        for (int i=0;i<TM;i++)
            #pragma unroll
            for (int j=0;j<TN;j++)
                wmma::store_matrix_sync(stage + (i*16)*WN + j*16, acc[i][j], WN,
                                        wmma::mem_row_major);
        __syncwarp();
        __half* Cw = (__half*)C + (size_t)(m0 + wr*WM)*ldc + n0 + wc*WN;
        const int lane = tid & 31;
        #pragma unroll 4
        for (int q = lane; q < WM*WN/2; q += 32) {
            int row = q / (WN/2);
            int cc  = (q % (WN/2))*2;
            float2 v = *(float2*)(stage + row*WN + cc);
            *(__half2*)(Cw + (size_t)row*ldc + cc) = __floats2half2_rn(v.x, v.y);
        }
    } else {
        #pragma unroll
        for (int i=0;i<TM;i++)
            #pragma unroll
            for (int j=0;j<TN;j++){
                float* cp = (float*)C + (size_t)(m0 + wr*WM + i*16)*ldc + n0 + wc*WN + j*16;
                wmma::store_matrix_sync(cp, acc[i][j], ldc, wmma::mem_row_major);
            }
    }
}

#define GH_BIG_PIPE  (3*(128*(32+8) + 128*(32+8))*2)
#define GH_BIG_STAGE (4*64*64*4)
#define GH_BIG_SMEM  (GH_BIG_STAGE > GH_BIG_PIPE ? GH_BIG_STAGE : GH_BIG_PIPE)
#define GH_XP_SMEM   (3*(64*(64+8) + 64*(64+8))*2)

// ---------------------------------------------------------------------------
// Causal depthwise conv (k=4) + bias + SiLU — rolling window, half2 channels.
// ---------------------------------------------------------------------------
__global__ __launch_bounds__(256)
void conv_silu_kernel(const __half* __restrict__ xz,
                      const float* __restrict__ cw,
                      const float* __restrict__ cb,
                      __half* __restrict__ u)
{
    int i = blockIdx.x*256 + threadIdx.x;
    if (i >= BB*(LL/LCH)*(DI/2)) return;
    int c2 = i & (DI/2 - 1);
    int t  = i >> 9;
    int lc = t & (LL/LCH - 1);
    int b  = t >> 6;
    int c  = c2*2;

    float4 wa = *(const float4*)(cw + c*DCONV);
    float4 wb = *(const float4*)(cw + (c+1)*DCONV);
    float cba = cb[c], cbb = cb[c+1];

    const int l0 = lc*LCH;
    const __half2* src = (const __half2*)xz + (size_t)(b*LL)*DI + c2;
    __half2* dst = (__half2*)u + (size_t)(b*LL)*(DI/2) + c2;

    float2 x0 = make_float2(0.f,0.f), x1 = x0, x2 = x0;
    if (l0 >= 3) {
        x0 = __half22float2(src[(size_t)(l0-3)*DI]);
        x1 = __half22float2(src[(size_t)(l0-2)*DI]);
        x2 = __half22float2(src[(size_t)(l0-1)*DI]);
    } else {
        if (l0-3 >= 0) x0 = __half22float2(src[(size_t)(l0-3)*DI]);
        if (l0-2 >= 0) x1 = __half22float2(src[(size_t)(l0-2)*DI]);
        if (l0-1 >= 0) x2 = __half22float2(src[(size_t)(l0-1)*DI]);
    }

    #pragma unroll 8
    for (int l = l0; l < l0+LCH; l++) {
        float2 x3 = __half22float2(src[(size_t)l*DI]);
        float va = cba, vb = cbb;
        va = fmaf(x0.x, wa.x, va); vb = fmaf(x0.y, wb.x, vb);
        va = fmaf(x1.x, wa.y, va); vb = fmaf(x1.y, wb.y, vb);
        va = fmaf(x2.x, wa.z, va); vb = fmaf(x2.y, wb.z, vb);
        va = fmaf(x3.x, wa.w, va); vb = fmaf(x3.y, wb.w, vb);
        va = va * fsigmoid(va);
        vb = vb * fsigmoid(vb);
        dst[(size_t)l*(DI/2)] = __floats2half2_rn(va, vb);
        x0 = x1; x1 = x2; x2 = x3;
    }
}

// ---------------------------------------------------------------------------
// Selective scan, chunked two-pass, dt-GEMM fused.
// Fast path stores only scalar Pp per (g, chain); full P only when !fast.
// ---------------------------------------------------------------------------
__global__ __launch_bounds__(128)
void scan_phaseA(const __half* __restrict__ u,
                 const float* __restrict__ xdbl,
                 const float* __restrict__ Wdt,
                 const float* __restrict__ bdt,
                 const float* __restrict__ Alog,
                 float* __restrict__ E,
                 float* __restrict__ P,
                 float* __restrict__ Pp)
{
    const int d = blockIdx.x*128 + threadIdx.x;
    const int g = blockIdx.y;
    const int b = blockIdx.z;
    const int chain = b*DI + d;

    __shared__ float sW[128*33];
    __shared__ float sX[16][XDW];

    {
        const float* wsrc = Wdt + (size_t)(blockIdx.x*128)*DTR;
        for (int idx = threadIdx.x; idx < 128*DTR; idx += 128) {
            int j = idx >> 5, r = idx & 31;
            sW[j*33 + r] = wsrc[idx];
        }
    }
    __syncthreads();
    float Wr[DTR];
    #pragma unroll
    for (int r=0;r<DTR;r++) Wr[r] = sW[threadIdx.x*33 + r];
    const float bd = bdt[d];

    float A[DS];
    const bool fast = fast_check(Alog, d, A);

    float h[DS], ap[DS];
    #pragma unroll
    for (int n=0;n<DS;n++) { h[n]=0.f; ap[n]=1.f; }
    float Ppv = 1.f;

    const int bl0 = b*LL + g*CLEN;

    for (int t0=0; t0<CLEN; t0+=16) {
        __syncthreads();
        for (int q=threadIdx.x; q<16*XDW; q+=128) {
            int j = q >> 6, m = q & 63;
            sX[j][m] = xdbl[(bl0+t0+j)*XDW + m];
        }
        __syncthreads();
        for (int t=0;t<16;t++) {
            int idx = bl0 + t0 + t;
            float v = bd;
            #pragma unroll
            for (int r=0;r<DTR;r++) v = fmaf(sX[t][r], Wr[r], v);
            float ldt = fsoftplus(v);
            float s   = ldt * __half2float(u[(size_t)idx*DI + d]);
            if (fast) {
                float p = fexp(ldt*A[0]);
                Ppv *= p;
                float pw = p;
                #pragma unroll
                for (int n=0;n<DS;n++) { h[n] = fmaf(pw, h[n], s*sX[t][DTR+n]); pw *= p; }
            } else {
                #pragma unroll
                for (int n=0;n<DS;n++) {
                    float a = fexp(ldt*A[n]);
                    ap[n] *= a;
                    h[n] = fmaf(a, h[n], s*sX[t][DTR+n]);
                }
            }
        }
    }
    #pragma unroll
    for (int n=0;n<DS;n++)
        E[(g*DS+n)*NCHAIN + chain] = h[n];
    if (fast) {
        Pp[g*NCHAIN + chain] = Ppv;
    } else {
        #pragma unroll
        for (int n=0;n<DS;n++)
            P[(g*DS+n)*NCHAIN + chain] = ap[n];
    }
}

// phaseB: one thread per (chain, state). Serial over 32 chunks.
__global__ void scan_phaseB(const float* __restrict__ E,
                            const float* __restrict__ P,
                            const float* __restrict__ Pp,
                            const float* __restrict__ Alog,
                            float* __restrict__ Hi)
{
    int i = blockIdx.x*256 + threadIdx.x;
    if (i >= NCHAIN*DS) return;
    int c = i & (NCHAIN-1);
    int n = i >> 13;                 // log2(NCHAIN)=13
    int d = c & (DI-1);

    float A[DS];
    const bool fast = fast_check(Alog, d, A);

    float carry = 0.f;
    #pragma unroll 4
    for (int g=0; g<NCHUNK; g++) {
        int o = (g*DS+n)*NCHAIN + c;
        Hi[o] = carry;
        float pg;
        if (fast) {
            float base = Pp[g*NCHAIN + c];
            pg = base;
            for (int k=0;k<n;k++) pg *= base;   // base^(n+1)
        } else {
            pg = P[o];
        }
        carry = fmaf(pg, carry, E[o]);
    }
}

__global__ __launch_bounds__(128)
void scan_phaseC(const __half* __restrict__ u,
                 const float* __restrict__ xdbl,
                 const __half* __restrict__ xz,
                 const float* __restrict__ Wdt,
                 const float* __restrict__ bdt,
                 const float* __restrict__ Alog,
                 const float* __restrict__ Dpar,
                 const float* __restrict__ Hi,
                 __half* __restrict__ yout)
{
    const int d = blockIdx.x*128 + threadIdx.x;
    const int g = blockIdx.y;
    const int b = blockIdx.z;
    const int chain = b*DI + d;

    __shared__ float sW[128*33];
    __shared__ float sX[16][XDW];

    {
        const float* wsrc = Wdt + (size_t)(blockIdx.x*128)*DTR;
        for (int idx = threadIdx.x; idx < 128*DTR; idx += 128) {
            int j = idx >> 5, r = idx & 31;
            sW[j*33 + r] = wsrc[idx];
        }
    }
    __syncthreads();
    float Wr[DTR];
    #pragma unroll
    for (int r=0;r<DTR;r++) Wr[r] = sW[threadIdx.x*33 + r];
    const float bd = bdt[d];

    float A[DS];
    const bool fast = fast_check(Alog, d, A);

    float h[DS];
    #pragma unroll
    for (int n=0;n<DS;n++) h[n] = Hi[(g*DS+n)*NCHAIN + chain];
    const float Dp = Dpar[d];

    const int bl0 = b*LL + g*CLEN;

    for (int t0=0; t0<CLEN; t0+=16) {
        __syncthreads();
        for (int q=threadIdx.x; q<16*XDW; q+=128) {
            int j = q >> 6, m = q & 63;
            sX[j][m] = xdbl[(bl0+t0+j)*XDW + m];
        }
        __syncthreads();
        for (int t=0;t<16;t++) {
            int idx = bl0 + t0 + t;
            float v = bd;
            #pragma unroll
            for (int r=0;r<DTR;r++) v = fmaf(sX[t][r], Wr[r], v);
            float ldt = fsoftplus(v);
            float lu  = __half2float(u[(size_t)idx*DI + d]);
            float s   = ldt * lu;
            float y   = 0.f;
            if (fast) {
                float p = fexp(ldt*A[0]);
                float pw = p;
                #pragma unroll
                for (int n=0;n<DS;n++) {
                    h[n] = fmaf(pw, h[n], s*sX[t][DTR+n]);
                    y    = fmaf(h[n], sX[t][DTR+DS+n], y);
                    pw *= p;
                }
            } else {
                #pragma unroll
                for (int n=0;n<DS;n++) {
                    float a = fexp(ldt*A[n]);
                    h[n] = fmaf(a, h[n], s*sX[t][DTR+n]);
                    y    = fmaf(h[n], sX[t][DTR+DS+n], y);
                }
            }
            float z = __half2float(xz[(size_t)idx*(2*DI) + DI + d]);
            yout[(size_t)idx*DI + d] = __float2half((y + lu*Dp) * z * fsigmoid(z));
        }
    }
}

// ---------------------------------------------------------------------------
// Head
// ---------------------------------------------------------------------------
__global__ void head_kernel(const __half* __restrict__ x,
                            const int* __restrict__ lens,
                            const float* __restrict__ W1,
                            const float* __restrict__ b1,
                            const float* __restrict__ W2,
                            const float* __restrict__ b2,
                            float* __restrict__ out)
{
    __shared__ float xs[DM];
    __shared__ float red[DHID];
    const int b = blockIdx.x;
    const int tid = threadIdx.x;
    const int l = lens[b] - 1;
    const __half* xr = x + ((size_t)(b*LL + l))*DM;
    for (int i=tid; i<DM; i+=DHID) xs[i] = __half2float(xr[i]);
    __syncthreads();
    float acc = b1[tid];
    const float* w = W1 + tid*DM;
    #pragma unroll 4
    for (int d0=0; d0<DM; d0+=4) {
        float4 wv = *(const float4*)(w + d0);
        acc = fmaf(wv.x, xs[d0+0], acc);
        acc = fmaf(wv.y, xs[d0+1], acc);
        acc = fmaf(wv.z, xs[d0+2], acc);
        acc = fmaf(wv.w, xs[d0+3], acc);
    }
    float hh = fmaxf(acc, 0.f);
    red[tid] = hh * W2[tid];
    __syncthreads();
    for (int s=DHID/2; s>0; s>>=1) {
        if (tid < s) red[tid] += red[tid+s];
        __syncthreads();
    }
    if (tid == 0) out[b] = red[0] + b2[0];
}

// ---------------------------------------------------------------------------
// Host launcher
// ---------------------------------------------------------------------------
extern "C" void kernel_launch(void* const* d_in, const int* in_sizes, int n_in,
                              void* d_out, int out_size)
{
    const int*   rna     = (const int*)  d_in[0];
    const int*   tissue  = (const int*)  d_in[1];
    const int*   lens    = (const int*)  d_in[2];
    const float* seq_emb = (const float*)d_in[3];
    const float* tis_emb = (const float*)d_in[4];
    const float* W_in    = (const float*)d_in[5];
    const float* conv_w  = (const float*)d_in[6];
    const float* conv_b  = (const float*)d_in[7];
    const float* W_xp    = (const float*)d_in[8];
    const float* W_dt    = (const float*)d_in[9];
    const float* b_dt    = (const float*)d_in[10];
    const float* A_log   = (const float*)d_in[11];
    const float* D_par   = (const float*)d_in[12];
    const float* W_out   = (const float*)d_in[13];
    const float* W1      = (const float*)d_in[14];
    const float* b1      = (const float*)d_in[15];
    const float* W2      = (const float*)d_in[16];
    const float* b2      = (const float*)d_in[17];

    __half *px0, *px1, *pxz, *pu, *py, *pWhin, *pWhxp, *pWhout;
    float  *pxd, *pE, *pP, *pPp, *pHi;
    cudaGetSymbolAddress((void**)&px0,   g_x0);
    cudaGetSymbolAddress((void**)&px1,   g_x1);
    cudaGetSymbolAddress((void**)&pxz,   g_xz);
    cudaGetSymbolAddress((void**)&pu,    g_u);
    cudaGetSymbolAddress((void**)&pxd,   g_xdbl);
    cudaGetSymbolAddress((void**)&py,    g_y);
    cudaGetSymbolAddress((void**)&pE,    g_E);
    cudaGetSymbolAddress((void**)&pP,    g_P);
    cudaGetSymbolAddress((void**)&pPp,   g_Pp);
    cudaGetSymbolAddress((void**)&pHi,   g_Hi);
    cudaGetSymbolAddress((void**)&pWhin, g_Whin);
    cudaGetSymbolAddress((void**)&pWhxp, g_Whxp);
    cudaGetSymbolAddress((void**)&pWhout,g_Whout);

    cudaFuncSetAttribute((gemm_h<128,128,32,64,64,128,__half>),
                         cudaFuncAttributeMaxDynamicSharedMemorySize, GH_BIG_SMEM);
    cudaFuncSetAttribute((gemm_h<64,64,64,32,32,128,float>),
                         cudaFuncAttributeMaxDynamicSharedMemorySize, GH_XP_SMEM);

    {
        int n1 = NL*2*DI*DM, n2 = NL*XDW*DI, n3 = NL*DM*DI;
        cvt_kernel<<<(n1+255)/256, 256>>>(W_in,  pWhin,  n1);
        cvt_kernel<<<(n2+255)/256, 256>>>(W_xp,  pWhxp,  n2);
        cvt_kernel<<<(n3+255)/256, 256>>>(W_out, pWhout, n3);
    }

    embed_kernel<<<(BLTOT*DM/8+255)/256, 256>>>(rna, tissue, seq_emb, tis_emb, px0);

    __half* xin  = px0;
    __half* xout = px1;
    for (int i=0; i<NL; i++) {
        // in-proj
        gemm_h<128,128,32,64,64,128,__half>
            <<<dim3((2*DI)/128, BLTOT/128), 128, GH_BIG_SMEM>>>(
            xin, DM, pWhin + (size_t)i*2*DI*DM, DM, pxz, 2*DI, DM);
        // conv + silu (rolling window)
        conv_silu_kernel<<<(BB*(LL/LCH)*(DI/2)+255)/256, 256>>>(
            pxz, conv_w + i*DI*DCONV, conv_b + i*DI, pu);
        // x-proj
        gemm_h<64,64,64,32,32,128,float>
            <<<dim3(XDW/64, BLTOT/64), 128, GH_XP_SMEM>>>(
            pu, DI, pWhxp + (size_t)i*XDW*DI, DI, pxd, XDW, DI);
        // selective scan
        scan_phaseA<<<dim3(DI/128, NCHUNK, BB), 128>>>(
            pu, pxd, W_dt + (size_t)i*DI*DTR, b_dt + i*DI,
            A_log + (size_t)i*DI*DS, pE, pP, pPp);
        scan_phaseB<<<(NCHAIN*DS+255)/256, 256>>>(pE, pP, pPp,
            A_log + (size_t)i*DI*DS, pHi);
        scan_phaseC<<<dim3(DI/128, NCHUNK, BB), 128>>>(
            pu, pxd, pxz, W_dt + (size_t)i*DI*DTR, b_dt + i*DI,
            A_log + (size_t)i*DI*DS, D_par + i*DI, pHi, py);
        // out-proj
        gemm_h<128,128,32,64,64,128,__half>
            <<<dim3(DM/128, BLTOT/128), 128, GH_BIG_SMEM>>>(
            py, DI, pWhout + (size_t)i*DM*DI, DI, xout, DM, DI);

        __half* tmp = xin; xin = xout; xout = tmp;
    }

    head_kernel<<<BB, DHID>>>(xin, lens, W1, b1, W2, b2, (float*)d_out);
}